// round 10
// baseline (speedup 1.0000x reference)
#include <cuda_runtime.h>
#include <cuda_bf16.h>
#include <cstdint>

#define BATCH 16
#define NQ 2048
#define NK 2048
#define DHEAD 128
#define KBLOCKS 16
#define INV_SQRT_SCALE 0.08838834764831845f  // 1/sqrt(128)

// ---------------------------------------------------------------------------
// Global scratch: pre-split bf16 hi/lo copies of q, k, v + bit-packed mask.
// ---------------------------------------------------------------------------
#define TENSOR_ELEMS ((size_t)BATCH * NQ * DHEAD)
__device__ __align__(16) __nv_bfloat16 g_qh[TENSOR_ELEMS];
__device__ __align__(16) __nv_bfloat16 g_ql[TENSOR_ELEMS];
__device__ __align__(16) __nv_bfloat16 g_kh[TENSOR_ELEMS];
__device__ __align__(16) __nv_bfloat16 g_kl[TENSOR_ELEMS];
__device__ __align__(16) __nv_bfloat16 g_vh[TENSOR_ELEMS];
__device__ __align__(16) __nv_bfloat16 g_vl[TENSOR_ELEMS];
__device__ float g_partial[(size_t)BATCH * NQ * KBLOCKS];
__device__ int g_mask_mode;   // 0 = bytes, 1 = int32, 2 = float32
#define MBITS_WORDS ((size_t)BATCH * NQ * NK / 32)
__device__ __align__(16) uint32_t g_mbits[MBITS_WORDS];

// ---------------------------------------------------------------------------
// K1 smem (64 q-rows x 128 k-cols tile): per buf Qh(5120) Ql(5120) Kh(10240)
// Kl(10240) = 30720; 2 bufs = 61440. Score staging 64x132 f32 = 33792 overlays.
// ---------------------------------------------------------------------------
#define K1_QH 0
#define K1_QL 5120
#define K1_KH 10240
#define K1_KL 20480
#define K1_BUF(b) ((b) * 30720)
#define SMEM_K1 61440
#define SCSTRIDE 132

// ---------------------------------------------------------------------------
// K2 smem (64 q-rows x 128 dhead tile): att bufs 2 x 9216 (64x144); V bufs
// 2 x 17408 @18432; E (64x32 h+l, stride 80) @53248; rd[64] @63488.
// Ctx staging 33792 overlays att+V bufs.
// ---------------------------------------------------------------------------
#define K2_ATT(b) ((b) * 9216)
#define K2_V(b) (18432 + (b) * 17408)      // vh 8704 + vl 8704
#define K2_OFF_E 53248                     // Eh 5120, El 5120
#define K2_ESTRIDE 80
#define K2_EL 5120
#define K2_OFF_RD 63488
#define SMEM_K2 63744

// ---------------------------------------------------------------------------
// PTX primitives (portable, base sm_103 target)
// ---------------------------------------------------------------------------
__device__ __forceinline__ uint32_t smem_u32(const void* p) {
    uint32_t a;
    asm("{ .reg .u64 t; cvta.to.shared.u64 t, %1; cvt.u32.u64 %0, t; }" : "=r"(a) : "l"(p));
    return a;
}
__device__ __forceinline__ void ldsm_x4(uint32_t a, uint32_t r[4]) {
    asm volatile("ldmatrix.sync.aligned.m8n8.x4.shared.b16 {%0,%1,%2,%3}, [%4];"
        : "=r"(r[0]), "=r"(r[1]), "=r"(r[2]), "=r"(r[3]) : "r"(a));
}
__device__ __forceinline__ void ldsm_x4t(uint32_t a, uint32_t r[4]) {
    asm volatile("ldmatrix.sync.aligned.m8n8.x4.trans.shared.b16 {%0,%1,%2,%3}, [%4];"
        : "=r"(r[0]), "=r"(r[1]), "=r"(r[2]), "=r"(r[3]) : "r"(a));
}
__device__ __forceinline__ void mma16816(float c[4], const uint32_t a[4], uint32_t b0, uint32_t b1) {
    asm volatile("mma.sync.aligned.m16n8k16.row.col.f32.bf16.bf16.f32 "
        "{%0,%1,%2,%3}, {%4,%5,%6,%7}, {%8,%9}, {%0,%1,%2,%3};"
        : "+f"(c[0]), "+f"(c[1]), "+f"(c[2]), "+f"(c[3])
        : "r"(a[0]), "r"(a[1]), "r"(a[2]), "r"(a[3]), "r"(b0), "r"(b1));
}
__device__ __forceinline__ void cp16(uint32_t dst, const void* src) {
    asm volatile("cp.async.cg.shared.global [%0], [%1], 16;" :: "r"(dst), "l"(src));
}
#define CP_COMMIT() asm volatile("cp.async.commit_group;")
#define CP_WAIT1()  asm volatile("cp.async.wait_group 1;")
#define CP_WAIT0()  asm volatile("cp.async.wait_group 0;")

__device__ __forceinline__ uint32_t pack2(__nv_bfloat16 a, __nv_bfloat16 b) {
    __nv_bfloat162 t = __halves2bfloat162(a, b);
    return *reinterpret_cast<uint32_t*>(&t);
}
__device__ __forceinline__ void split2(float x, float y, uint32_t& h, uint32_t& l) {
    __nv_bfloat16 hx = __float2bfloat16(x), hy = __float2bfloat16(y);
    __nv_bfloat16 lx = __float2bfloat16(x - __bfloat162float(hx));
    __nv_bfloat16 ly = __float2bfloat16(y - __bfloat162float(hy));
    h = pack2(hx, hy);
    l = pack2(lx, ly);
}

// ---------------------------------------------------------------------------
__global__ void detect_mask_kernel(const unsigned char* __restrict__ m)
{
    const int tid = threadIdx.x;
    int mis = 0, ftail = 0;
    for (int i = tid * 16; i < tid * 16 + 16; i++) {
        const unsigned char b = m[i];
        if (b) {
            const int r = i & 3;
            if (r == 1) mis = 1;
            else if (r == 2) { if (b != 0x80) mis = 1; else ftail = 1; }
            else if (r == 3) { if (b != 0x3F) mis = 1; else ftail = 1; }
        }
    }
    const int anyMis = __syncthreads_or(mis);
    const int anyF   = __syncthreads_or(ftail);
    if (tid == 0) g_mask_mode = anyMis ? 0 : (anyF ? 2 : 1);
}

__global__ __launch_bounds__(256) void pack_mask_kernel(const void* __restrict__ mask)
{
    const size_t w = (size_t)blockIdx.x * 256 + threadIdx.x;
    const int mode = g_mask_mode;
    uint32_t bits = 0;
    if (mode == 0) {
        const uint4* p = (const uint4*)((const unsigned char*)mask + w * 32);
#pragma unroll
        for (int i = 0; i < 2; i++) {
            const uint4 v = p[i];
            const uint32_t ws[4] = {v.x, v.y, v.z, v.w};
#pragma unroll
            for (int k = 0; k < 4; k++)
#pragma unroll
                for (int byt = 0; byt < 4; byt++)
                    bits |= (uint32_t)(((ws[k] >> (8 * byt)) & 0xffu) != 0u) << (i * 16 + k * 4 + byt);
        }
    } else {
        const uint4* p = (const uint4*)((const uint32_t*)mask + w * 32);
#pragma unroll
        for (int i = 0; i < 8; i++) {
            const uint4 v = p[i];
            bits |= (uint32_t)(v.x != 0u) << (i * 4 + 0);
            bits |= (uint32_t)(v.y != 0u) << (i * 4 + 1);
            bits |= (uint32_t)(v.z != 0u) << (i * 4 + 2);
            bits |= (uint32_t)(v.w != 0u) << (i * 4 + 3);
        }
    }
    g_mbits[w] = bits;
}

__global__ __launch_bounds__(256) void prep_kernel(
    const float* __restrict__ q, const float* __restrict__ k, const float* __restrict__ v)
{
    const size_t t = (size_t)blockIdx.x * 256 + threadIdx.x;   // float4 index
    const float* src;
    __nv_bfloat16 *dh, *dl;
    if (blockIdx.y == 0)      { src = q; dh = g_qh; dl = g_ql; }
    else if (blockIdx.y == 1) { src = k; dh = g_kh; dl = g_kl; }
    else                      { src = v; dh = g_vh; dl = g_vl; }
    const float4 x = ((const float4*)src)[t];
    uint32_t h01, l01, h23, l23;
    split2(x.x, x.y, h01, l01);
    split2(x.z, x.w, h23, l23);
    ((uint2*)dh)[t] = make_uint2(h01, h23);
    ((uint2*)dl)[t] = make_uint2(l01, l23);
}

// ---------------------------------------------------------------------------
// K1: tile 64 q-rows x 128 k-cols; 8 warps (2x4), warp tile 32x32.
// D streamed in 4 chunks of 32, cp.async double-buffered. 3 CTAs/SM.
// ---------------------------------------------------------------------------
__device__ __forceinline__ void k1_issue(uint32_t sb, int b, int q0, int k0, int ic, int buf, int tid)
{
    const int d0 = ic * 32;
#pragma unroll
    for (int i = 0; i < 6; i++) {
        const int idx = i * 256 + tid;     // 0..1535
        if (idx < 512) {                   // Q h/l: 64 rows x 4 c16
            const int h = idx >> 8;
            const int r = (idx >> 2) & 63;
            const int c = idx & 3;
            const __nv_bfloat16* base = h ? g_ql : g_qh;
            cp16(sb + K1_BUF(buf) + h * 5120 + r * 80 + c * 16,
                 base + ((size_t)(b * NQ + q0 + r)) * DHEAD + d0 + c * 8);
        } else {                           // K h/l: 128 rows x 4 c16
            const int j = idx - 512;       // 0..1023
            const int h = j >> 9;
            const int r = (j >> 2) & 127;
            const int c = j & 3;
            const __nv_bfloat16* base = h ? g_kl : g_kh;
            cp16(sb + K1_BUF(buf) + K1_KH + h * 10240 + r * 80 + c * 16,
                 base + ((size_t)(b * NQ + k0 + r)) * DHEAD + d0 + c * 8);
        }
    }
}

__global__ __launch_bounds__(256, 3)
void qk_exp_kernel(float* __restrict__ att)
{
    extern __shared__ char smem[];
    const uint32_t sb = smem_u32(smem);
    const int tid = threadIdx.x;
    const int wid = tid >> 5;
    const int lane = tid & 31;
    const int wm = wid >> 2;    // 0/1 -> 32-row half
    const int wn = wid & 3;     // 0..3 -> 32-col group

    const int b  = blockIdx.z;
    const int q0 = blockIdx.y * 64;
    const int k0 = blockIdx.x * 128;

    k1_issue(sb, b, q0, k0, 0, 0, tid); CP_COMMIT();
    k1_issue(sb, b, q0, k0, 1, 1, tid); CP_COMMIT();

    float acc[2][4][4];
#pragma unroll
    for (int mt = 0; mt < 2; mt++)
#pragma unroll
        for (int g = 0; g < 4; g++)
#pragma unroll
            for (int r = 0; r < 4; r++) acc[mt][g][r] = 0.0f;

    const int lm = lane & 15, lq = lane >> 4;

    for (int ic = 0; ic < 4; ic++) {
        const int buf = ic & 1;
        if (ic < 3) { CP_WAIT1(); } else { CP_WAIT0(); }
        __syncthreads();

        const uint32_t qb = sb + K1_BUF(buf);
        const uint32_t kb = sb + K1_BUF(buf) + K1_KH;
#pragma unroll
        for (int ks = 0; ks < 2; ks++) {
            uint32_t ah[2][4], al[2][4], kh[2][4], kl[2][4];
#pragma unroll
            for (int mt = 0; mt < 2; mt++) {
                const uint32_t a = qb + (wm * 32 + mt * 16 + lm) * 80 + (ks * 16 + lq * 8) * 2;
                ldsm_x4(a, ah[mt]);
                ldsm_x4(a + 5120, al[mt]);
            }
#pragma unroll
            for (int np = 0; np < 2; np++) {
                const uint32_t a = kb + (wn * 32 + np * 16 + lm) * 80 + (ks * 16 + lq * 8) * 2;
                ldsm_x4(a, kh[np]);
                ldsm_x4(a + 10240, kl[np]);
            }
            // b-frag for n8 group g: np=g>>1, sub=g&1 -> {k[np][sub], k[np][sub+2]}
#pragma unroll
            for (int mt = 0; mt < 2; mt++)
#pragma unroll
                for (int g = 0; g < 4; g++) {
                    const int np = g >> 1, su = g & 1;
                    mma16816(acc[mt][g], ah[mt], kh[np][su], kh[np][su + 2]);
                    mma16816(acc[mt][g], ah[mt], kl[np][su], kl[np][su + 2]);
                    mma16816(acc[mt][g], al[mt], kh[np][su], kh[np][su + 2]);
                }
        }
        __syncthreads();
        if (ic + 2 < 4) { k1_issue(sb, b, q0, k0, ic + 2, (ic + 2) & 1, tid); CP_COMMIT(); }
    }

    // Stage scores through smem (overlays buffers; all loads consumed).
    float* sc = (float*)smem;
    {
        const int r0 = lane >> 2;
        const int c0 = (lane & 3) * 2;
#pragma unroll
        for (int mt = 0; mt < 2; mt++)
#pragma unroll
            for (int g = 0; g < 4; g++) {
                const int rr = wm * 32 + mt * 16 + r0;
                const int cc = wn * 32 + g * 8 + c0;
                sc[rr * SCSTRIDE + cc]           = acc[mt][g][0];
                sc[rr * SCSTRIDE + cc + 1]       = acc[mt][g][1];
                sc[(rr + 8) * SCSTRIDE + cc]     = acc[mt][g][2];
                sc[(rr + 8) * SCSTRIDE + cc + 1] = acc[mt][g][3];
            }
    }
    __syncthreads();

    {
        const int row = tid & 63;
        const int qtr = tid >> 6;          // 0..3 -> 32-col group
        const size_t roff = ((size_t)b * NQ + q0 + row) * NK + k0 + qtr * 32;
        const uint32_t mw = g_mbits[((size_t)b * NQ + q0 + row) * (NK / 32) + (k0 >> 5) + qtr];
        float rsum = 0.0f;
#pragma unroll
        for (int j = 0; j < 8; j++) {
            const float4 s4 = *(const float4*)&sc[row * SCSTRIDE + qtr * 32 + j * 4];
            const int sh = j * 4;
            float e[4];
            const float ss[4] = {s4.x, s4.y, s4.z, s4.w};
#pragma unroll
            for (int jj = 0; jj < 4; jj++)
                e[jj] = ((mw >> (sh + jj)) & 1u) ? 0.0f : __expf(ss[jj] * INV_SQRT_SCALE);
            rsum += (e[0] + e[1]) + (e[2] + e[3]);
            *(float4*)(att + roff + j * 4) = make_float4(e[0], e[1], e[2], e[3]);
        }
        sc[row * SCSTRIDE + 128 + qtr] = rsum;
    }
    __syncthreads();
    if (tid < 64)
        g_partial[((size_t)b * NQ + q0 + tid) * KBLOCKS + blockIdx.x] =
            (sc[tid * SCSTRIDE + 128] + sc[tid * SCSTRIDE + 129]) +
            (sc[tid * SCSTRIDE + 130] + sc[tid * SCSTRIDE + 131]);
}

// ---------------------------------------------------------------------------
// K2: tile 64 q-rows x 128 dhead; normalize att in place; ctx = att @ V.
// NK streamed in 32-key chunks, cp.async double-buffered. 3 CTAs/SM.
// ---------------------------------------------------------------------------
__device__ __forceinline__ void k2_issue(uint32_t sb, const float* attbase, int b, int ic, int buf, int tid)
{
    const int n0 = ic * 32;
#pragma unroll
    for (int i = 0; i < 6; i++) {
        const int idx = i * 256 + tid;     // 0..1535
        if (idx < 512) {                   // att fp32 chunk: 64 rows x 8 c16
            const int r = idx >> 3;
            const int c = idx & 7;
            cp16(sb + K2_ATT(buf) + r * 144 + c * 16,
                 attbase + (size_t)r * NK + n0 + c * 4);
        } else {                           // V h/l: 32 rows x 16 c16 each
            const int j = idx - 512;
            const int h = j >> 9;
            const int r = (j >> 4) & 31;
            const int c = j & 15;
            const __nv_bfloat16* base = h ? g_vl : g_vh;
            cp16(sb + K2_V(buf) + h * 8704 + r * 272 + c * 16,
                 base + ((size_t)(b * NQ + n0 + r)) * DHEAD + c * 8);
        }
    }
}

__global__ __launch_bounds__(256, 3)
void av_kernel(float* __restrict__ att, float* __restrict__ ctx)
{
    extern __shared__ char smem[];
    const uint32_t sb = smem_u32(smem);
    float* rd = (float*)(smem + K2_OFF_RD);
    const int tid = threadIdx.x;
    const int wid = tid >> 5;
    const int lane = tid & 31;
    const int wm = wid >> 2;    // 0/1
    const int wn = wid & 3;     // 0..3

    const int b  = blockIdx.y;
    const int q0 = blockIdx.x * 64;

    if (tid < 64) {
        const float* p = &g_partial[((size_t)b * NQ + q0 + tid) * KBLOCKS];
        float s = 0.0f;
#pragma unroll
        for (int i = 0; i < KBLOCKS; i++) s += p[i];
        rd[tid] = 1.0f / s;
    }

    float* attbase = att + ((size_t)b * NQ + q0) * NK;
    k2_issue(sb, attbase, b, 0, 0, tid); CP_COMMIT();
    k2_issue(sb, attbase, b, 1, 1, tid); CP_COMMIT();

    float acc[2][4][4];
#pragma unroll
    for (int mt = 0; mt < 2; mt++)
#pragma unroll
        for (int g = 0; g < 4; g++)
#pragma unroll
            for (int r = 0; r < 4; r++) acc[mt][g][r] = 0.0f;

    const int lm = lane & 15, lq = lane >> 4;

    for (int ic = 0; ic < NK / 32; ic++) {
        const int buf = ic & 1;
        const int n0 = ic * 32;
        if (ic < NK / 32 - 1) { CP_WAIT1(); } else { CP_WAIT0(); }
        __syncthreads();

        // Normalize att chunk (write back to global) + split into E tiles.
#pragma unroll
        for (int i = 0; i < 2; i++) {
            const int idx = i * 256 + tid;    // 0..511
            const int r = idx >> 3;
            const int c4 = idx & 7;
            float4 e = *(const float4*)(smem + K2_ATT(buf) + r * 144 + c4 * 16);
            const float rr = rd[r];
            e.x *= rr; e.y *= rr; e.z *= rr; e.w *= rr;
            *(float4*)(attbase + (size_t)r * NK + n0 + c4 * 4) = e;
            uint32_t hh0, ll0, hh1, ll1;
            split2(e.x, e.y, hh0, ll0);
            split2(e.z, e.w, hh1, ll1);
            *(uint2*)(smem + K2_OFF_E + r * K2_ESTRIDE + c4 * 8)         = make_uint2(hh0, hh1);
            *(uint2*)(smem + K2_OFF_E + K2_EL + r * K2_ESTRIDE + c4 * 8) = make_uint2(ll0, ll1);
        }
        __syncthreads();

        const uint32_t vb = sb + K2_V(buf);
#pragma unroll
        for (int ks = 0; ks < 2; ks++) {
            uint32_t eh[2][4], el[2][4], vh[2][4], vl[2][4];
#pragma unroll
            for (int mt = 0; mt < 2; mt++) {
                const uint32_t a = sb + K2_OFF_E + (wm * 32 + mt * 16 + lm) * K2_ESTRIDE
                                 + (ks * 16 + lq * 8) * 2;
                ldsm_x4(a, eh[mt]);
                ldsm_x4(a + K2_EL, el[mt]);
            }
#pragma unroll
            for (int np = 0; np < 2; np++) {
                const uint32_t a = vb + (ks * 16 + lm) * 272 + (wn * 32 + np * 16 + lq * 8) * 2;
                ldsm_x4t(a, vh[np]);
                ldsm_x4t(a + 8704, vl[np]);
            }
            // b-frag for n8 group g: np=g>>1, sub=g&1 -> {v[np][sub*2], v[np][sub*2+1]}
#pragma unroll
            for (int mt = 0; mt < 2; mt++)
#pragma unroll
                for (int g = 0; g < 4; g++) {
                    const int np = g >> 1, su = g & 1;
                    mma16816(acc[mt][g], eh[mt], vh[np][su * 2], vh[np][su * 2 + 1]);
                    mma16816(acc[mt][g], eh[mt], vl[np][su * 2], vl[np][su * 2 + 1]);
                    mma16816(acc[mt][g], el[mt], vh[np][su * 2], vh[np][su * 2 + 1]);
                }
        }
        __syncthreads();
        if (ic + 2 < NK / 32) { k2_issue(sb, attbase, b, ic + 2, (ic + 2) & 1, tid); CP_COMMIT(); }
    }

    // Stage ctx through smem for coalesced writes (overlays buffers).
    float* sc = (float*)smem;
    {
        const int r0 = lane >> 2;
        const int c0 = (lane & 3) * 2;
#pragma unroll
        for (int mt = 0; mt < 2; mt++)
#pragma unroll
            for (int g = 0; g < 4; g++) {
                const int rr = wm * 32 + mt * 16 + r0;
                const int cc = wn * 32 + g * 8 + c0;
                sc[rr * SCSTRIDE + cc]           = acc[mt][g][0];
                sc[rr * SCSTRIDE + cc + 1]       = acc[mt][g][1];
                sc[(rr + 8) * SCSTRIDE + cc]     = acc[mt][g][2];
                sc[(rr + 8) * SCSTRIDE + cc + 1] = acc[mt][g][3];
            }
    }
    __syncthreads();
    {
        const int row = tid & 63;
        const int qtr = tid >> 6;
        float* o = ctx + ((size_t)b * NQ + q0 + row) * DHEAD + qtr * 32;
#pragma unroll
        for (int j = 0; j < 8; j++)
            *(float4*)(o + j * 4) = *(const float4*)&sc[row * SCSTRIDE + qtr * 32 + j * 4];
    }
}

// ---------------------------------------------------------------------------
extern "C" void kernel_launch(void* const* d_in, const int* in_sizes, int n_in,
                              void* d_out, int out_size)
{
    const float* q = (const float*)d_in[0];
    const float* k = (const float*)d_in[1];
    const float* v = (const float*)d_in[2];
    const void*  mask = d_in[3];

    float* out = (float*)d_out;
    float* ctx = out;                                   // [B, NQ, D]
    float* att = out + (size_t)BATCH * NQ * DHEAD;      // [B, NQ, NK]

    cudaFuncSetAttribute(qk_exp_kernel, cudaFuncAttributeMaxDynamicSharedMemorySize, SMEM_K1);
    cudaFuncSetAttribute(av_kernel,     cudaFuncAttributeMaxDynamicSharedMemorySize, SMEM_K2);

    detect_mask_kernel<<<1, 256>>>((const unsigned char*)mask);
    pack_mask_kernel<<<(int)(MBITS_WORDS / 256), 256>>>(mask);
    prep_kernel<<<dim3(4096, 3), 256>>>(q, k, v);

    dim3 g1(NK / 128, NQ / 64, BATCH);
    qk_exp_kernel<<<g1, 256, SMEM_K1>>>(att);

    dim3 g2(NQ / 64, BATCH);
    av_kernel<<<g2, 256, SMEM_K2>>>(att, ctx);
}